// round 14
// baseline (speedup 1.0000x reference)
#include <cuda_runtime.h>

#define N_ 4
#define C_ 128
#define T_ 512
#define V_ 25
#define H_ 16
#define O_ 128
#define EPS_ 1e-5f
#define YCNT 51200.0f   // N*T*V

typedef unsigned long long ull;

// ---------------- scratch ----------------------------------------------------
__device__ float g_q[N_ * T_ * H_];              // [n][t][h]
__device__ float g_k[N_ * T_ * H_];              // [n][t][h]
__device__ float g_wvt[C_ * O_];                 // [c][o]
__device__ float g_v[N_ * T_ * O_ * 32];         // [n][t][o][32]
__device__ float g_vsum[N_ * O_ * 32];           // [n][o][32]
__device__ float g_s[(size_t)N_ * 32 * 32 * 4096]; // [n][gt][c32][g16][tt16][h16] = 64MB
__device__ float g_y[(size_t)N_ * O_ * T_ * 26]; // [n][o][g][26]
__device__ float g_chsum[O_];
__device__ float g_chsq[O_];

// ---------------- helpers -----------------------------------------------------
__device__ __forceinline__ ull ffma2(ull a, ull b, ull c) {
    ull d; asm("fma.rn.f32x2 %0, %1, %2, %3;" : "=l"(d) : "l"(a), "l"(b), "l"(c)); return d;
}
__device__ __forceinline__ ull fmul2(ull a, ull b) {
    ull d; asm("mul.rn.f32x2 %0, %1, %2;" : "=l"(d) : "l"(a), "l"(b)); return d;
}
__device__ __forceinline__ ull fadd2(ull a, ull b) {
    ull d; asm("add.rn.f32x2 %0, %1, %2;" : "=l"(d) : "l"(a), "l"(b)); return d;
}
__device__ __forceinline__ ull dup2(float x) {
    ull d; asm("mov.b64 %0, {%1, %1};" : "=l"(d) : "f"(x)); return d;
}
__device__ __forceinline__ float2 unpack2(ull a) {
    float2 r; asm("mov.b64 {%0, %1}, %2;" : "=f"(r.x), "=f"(r.y) : "l"(a)); return r;
}
__device__ __forceinline__ float tanh_fast(float x) {
    float r; asm("tanh.approx.f32 %0, %1;" : "=f"(r) : "f"(x)); return r;
}
__device__ __forceinline__ void cp16(float* dst, const float* src) {
    unsigned du = (unsigned)__cvta_generic_to_shared(dst);
    asm volatile("cp.async.ca.shared.global [%0], [%1], 16;" :: "r"(du), "l"(src));
}
#define CP_COMMIT() asm volatile("cp.async.commit_group;")
#define CP_WAIT1()  asm volatile("cp.async.wait_group 1;")
#define CP_WAIT2()  asm volatile("cp.async.wait_group 2;")

// ---------------- K0: prep (zero vsum + BN accumulators, transpose Wv) ---------
__global__ void prep_kernel(const float* __restrict__ Wv) {
    int b = blockIdx.x, tid = threadIdx.x;
    int i = b * 128 + tid;          // 0..16383
    g_vsum[i] = 0.f;                // exactly N*O*32 = 16384
    int o = i >> 7, c = i & 127;
    g_wvt[c * O_ + o] = Wv[i];
    if (b == 0) { g_chsum[tid] = 0.f; g_chsq[tid] = 0.f; }
}

// ---------------- K1: fused x-load -> xm -> q,k -> v (+vsum atomics) -----------
__global__ void qkv_kernel(const float* __restrict__ x,
                           const float* __restrict__ Wq, const float* __restrict__ bq,
                           const float* __restrict__ Wk, const float* __restrict__ bk,
                           const float* __restrict__ bv) {
    __shared__ float xs[C_][28];
    __shared__ float xm[C_];
    int b = blockIdx.x; int n = b >> 9; int t = b & 511;
    int o = threadIdx.x;
    {
        const float* xp = x + ((n * C_ + o) * T_ + t) * V_;
        float s = 0.f;
#pragma unroll
        for (int v = 0; v < V_; v++) { float xv = xp[v]; xs[o][v] = xv; s += xv; }
        xs[o][25] = 0.f; xs[o][26] = 0.f; xs[o][27] = 0.f;
        xm[o] = s * (1.0f / 25.0f);
    }
    __syncthreads();

    if (o < 32) {
        int h = o & 15;
        bool isQ = o < 16;
        const float* W = isQ ? Wq : Wk;
        float acc = isQ ? bq[h] : bk[h];
#pragma unroll 8
        for (int cc = 0; cc < C_; cc++) acc += W[h * C_ + cc] * xm[cc];
        float* dst = isQ ? g_q : g_k;
        dst[(n * T_ + t) * H_ + h] = acc;
    }

    ull acc[13];
    ull binit = dup2(bv[o]);
#pragma unroll
    for (int j = 0; j < 13; j++) acc[j] = binit;
    for (int c = 0; c < C_; c++) {
        ull wd = dup2(g_wvt[c * O_ + o]);
        const ulonglong2* xr = (const ulonglong2*)xs[c];
#pragma unroll
        for (int j = 0; j < 6; j++) {
            ulonglong2 p = xr[j];
            acc[2 * j]     = ffma2(wd, p.x, acc[2 * j]);
            acc[2 * j + 1] = ffma2(wd, p.y, acc[2 * j + 1]);
        }
        acc[12] = ffma2(wd, *((const ull*)xs[c] + 12), acc[12]);
    }
    float* row = g_v + (((size_t)(n * T_ + t)) * O_ + o) * 32;
    float* vs = g_vsum + (n * O_ + o) * 32;
#pragma unroll
    for (int j = 0; j < 12; j++) {
        float2 u = unpack2(acc[j]);
        row[2 * j] = u.x; row[2 * j + 1] = u.y;
        atomicAdd(&vs[2 * j], u.x);
        atomicAdd(&vs[2 * j + 1], u.y);
    }
    { float2 u = unpack2(acc[12]); row[24] = u.x; atomicAdd(&vs[24], u.x); }
#pragma unroll
    for (int p = 25; p < 32; p++) row[p] = 0.f;
}

// ---------------- K2: sv_kernel — S precompute only (512 balanced blocks) -------
// block = (n4, gt32, cq4); thread float4 f = tid + p*512 -> (g = f>>6, tt = (f>>2)&15, hq = f&3)
__global__ void __launch_bounds__(512)
sv_kernel() {
    int b = blockIdx.x;
    int n = b >> 7, gt = (b >> 2) & 31, cq = b & 3;
    int tid = threadIdx.x;
    float4 q4[2];
#pragma unroll
    for (int p = 0; p < 2; p++) {
        int f = tid + p * 512;
        int hq = f & 3, g = f >> 6;
        q4[p] = *(const float4*)(g_q + (n * T_ + gt * 16 + g) * H_ + hq * 4);
    }
    float* sb = g_s + ((size_t)((n * 32 + gt) * 32)) * 4096;
    for (int cc = cq * 8; cc < cq * 8 + 8; cc++) {
#pragma unroll
        for (int p = 0; p < 2; p++) {
            int f = tid + p * 512;
            int hq = f & 3, tt = (f >> 2) & 15;
            float4 k4 = *(const float4*)(g_k + (n * T_ + cc * 16 + tt) * H_ + hq * 4);
            float4 s;
            s.x = tanh_fast(q4[p].x - k4.x);
            s.y = tanh_fast(q4[p].y - k4.y);
            s.z = tanh_fast(q4[p].z - k4.z);
            s.w = tanh_fast(q4[p].w - k4.w);
            *(float4*)(sb + (size_t)cc * 4096 + f * 4) = s;
        }
    }
}

// ---------------- K3: fused attention — TCH=16, one barrier per chunk -----------
#define TCH 16
#define NCHUNK (T_ / TCH)            // 32
#define SCH 4096                     // S chunk floats (16g x 16tt x 16h)
#define AROW 260                     // 16tt*16g + 4 pad
#define ABUF (16 * AROW)             // 4160
#define SM_AS (3 * SCH)              // 12288
#define SM_TOT (SM_AS + 2 * ABUF)    // 20608 floats = 82432 B

// B stage: thread (oB16, ttB16, gq2) -> A[oB][ttB][gq*8..+7]
__device__ __forceinline__ void b_stage(const float* __restrict__ Sb, float* __restrict__ Ab,
                                        const ull* __restrict__ w, int oB, int ttB, int gq) {
    float outv[8];
    const float* srow = Sb + ttB * 16;
#pragma unroll
    for (int i = 0; i < 8; i++) {
        int g = gq * 8 + i;
        const ulonglong2* sp = (const ulonglong2*)(srow + g * 256);
        ulonglong2 s0 = sp[0], s1 = sp[1];
        ull a0 = fmul2(w[0], s0.x);  a0 = ffma2(w[1], s0.y, a0);
        a0 = ffma2(w[2], s1.x, a0);  a0 = ffma2(w[3], s1.y, a0);
        ulonglong2 s2 = sp[2], s3 = sp[3];
        ull a1 = fmul2(w[4], s2.x);  a1 = ffma2(w[5], s2.y, a1);
        a1 = ffma2(w[6], s3.x, a1);  a1 = ffma2(w[7], s3.y, a1);
        float2 u = unpack2(fadd2(a0, a1));
        outv[i] = u.x + u.y;
    }
    float* dst = Ab + oB * AROW + ttB * 16 + gq * 8;
    *(float4*)(dst)     = make_float4(outv[0], outv[1], outv[2], outv[3]);
    *(float4*)(dst + 4) = make_float4(outv[4], outv[5], outv[6], outv[7]);
}

// C half: 8 tt starting at tt0; scalar v, acc = 8 f32x2 pairs over g
__device__ __forceinline__ void c_half(const float* __restrict__ Ab, int oC, int tt0,
                                       const float* __restrict__ vc, ull* __restrict__ acc) {
    const float* arow = Ab + oC * AROW + tt0 * 16;
#pragma unroll
    for (int tt = 0; tt < 8; tt++) {
        const ulonglong2* ap = (const ulonglong2*)(arow + tt * 16);
        ull d = dup2(vc[tt]);
        ulonglong2 p0 = ap[0], p1 = ap[1];
        acc[0] = ffma2(p0.x, d, acc[0]);
        acc[1] = ffma2(p0.y, d, acc[1]);
        acc[2] = ffma2(p1.x, d, acc[2]);
        acc[3] = ffma2(p1.y, d, acc[3]);
        ulonglong2 p2 = ap[2], p3 = ap[3];
        acc[4] = ffma2(p2.x, d, acc[4]);
        acc[5] = ffma2(p2.y, d, acc[5]);
        acc[6] = ffma2(p3.x, d, acc[6]);
        acc[7] = ffma2(p3.y, d, acc[7]);
    }
}

__global__ void __launch_bounds__(512, 2)
attn_kernel(const float* __restrict__ Wr, const float* __restrict__ br) {
    extern __shared__ float sm[];
    float* S_s = sm;                 // 3 x 4096
    float* A_s = sm + SM_AS;         // 2 x 4160

    int bx = blockIdx.x;
    int gt = bx & 31, ot = (bx >> 5) & 7, n = bx >> 8;
    int o_base = ot * 16, g_base = gt * 16;
    int tid = threadIdx.x;

    // roles
    int oB = tid & 15, ttB = (tid >> 4) & 15, gq = tid >> 8;   // B: 8 g each
    int oC = tid / 26, vC = tid - oC * 26;                     // C (tid<416)
    bool actC = tid < 416;

    const float* sg = g_s + ((size_t)((n * 32 + gt) * 32)) * SCH + tid * 4;
    float* sd = S_s + tid * 4;

    ull w[8];
    {
        const ull* wp = (const ull*)(Wr + (o_base + oB) * H_);
#pragma unroll
        for (int j = 0; j < 8; j++) w[j] = wp[j];
    }

    ull acc[8];
    float vcur[8];
    const float* vbase = actC
        ? g_v + (((size_t)n * T_) * O_ + o_base + oC) * 32 + vC
        : g_v;
    if (actC) {
        float brv = br[o_base + oC];
        float vs = g_vsum[(n * O_ + o_base + oC) * 32 + vC];
        ull i0 = dup2(brv * vs);
#pragma unroll
        for (int p = 0; p < 8; p++) acc[p] = i0;
#pragma unroll
        for (int tt = 0; tt < 8; tt++)
            vcur[tt] = vbase[(size_t)tt * O_ * 32];   // v[c=0][tt 0..7]
    }

    // prologue: 3 chunk loads, one commit group each (2 cp16 per group)
    cp16(sd + 0 * SCH, sg + (size_t)0 * SCH);
    cp16(sd + 0 * SCH + 2048, sg + (size_t)0 * SCH + 2048);
    CP_COMMIT();
    cp16(sd + 1 * SCH, sg + (size_t)1 * SCH);
    cp16(sd + 1 * SCH + 2048, sg + (size_t)1 * SCH + 2048);
    CP_COMMIT();
    cp16(sd + 2 * SCH, sg + (size_t)2 * SCH);
    cp16(sd + 2 * SCH + 2048, sg + (size_t)2 * SCH + 2048);
    CP_COMMIT();
    CP_WAIT2();            // own S0 done
    __syncthreads();       // all S0 done
    b_stage(S_s, A_s, w, oB, ttB, gq);       // A(0) -> buf0
    CP_WAIT1();            // own S1 done
    __syncthreads();       // all S1 done + A0 visible

    // main loop: invariant at chunk c: S(c+1) done, A(c) visible, pending={S(c+2)}
    int sb = 0;
    for (int c = 0; c < NCHUNK; c++) {
        int ab = c & 1;
        if (c + 3 < NCHUNK) {
            cp16(sd + sb * SCH, sg + (size_t)(c + 3) * SCH);
            cp16(sd + sb * SCH + 2048, sg + (size_t)(c + 3) * SCH + 2048);
        }
        CP_COMMIT();       // uniform group count
        int rb = sb + 1; if (rb == 3) rb = 0;
        if (c + 1 < NCHUNK)
            b_stage(S_s + rb * SCH, A_s + (ab ^ 1) * ABUF, w, oB, ttB, gq);
        if (actC) {
            const float* Ab = A_s + ab * ABUF;
            c_half(Ab, oC, 0, vcur, acc);
            {   // reload vcur <- v[c][tt 8..15]
                const float* vb1 = vbase + ((size_t)c * TCH + 8) * O_ * 32;
#pragma unroll
                for (int tt = 0; tt < 8; tt++)
                    vcur[tt] = vb1[(size_t)tt * O_ * 32];
            }
            c_half(Ab, oC, 8, vcur, acc);
            if (c + 1 < NCHUNK) {   // prefetch v[c+1][tt 0..7]
                const float* vb2 = vbase + ((size_t)(c + 1) * TCH) * O_ * 32;
#pragma unroll
                for (int tt = 0; tt < 8; tt++)
                    vcur[tt] = vb2[(size_t)tt * O_ * 32];
            }
        }
        CP_WAIT1();        // own S(c+2) done
        __syncthreads();   // all S(c+2) done + A(c+1) visible
        sb = rb;
    }

    // ---- epilogue: y writes + BN partial stats ----
    float sum = 0.f, sq = 0.f;
    if (actC) {
        int o0 = o_base + oC;
        float* ybase = g_y + (((size_t)(n * O_ + o0)) * T_ + g_base) * 26 + vC;
#pragma unroll
        for (int p = 0; p < 8; p++) {
            float2 u = unpack2(acc[p]);
            ybase[(2 * p) * 26]     = u.x;
            ybase[(2 * p + 1) * 26] = u.y;
            sum += u.x + u.y;
            sq  += u.x * u.x + u.y * u.y;
        }
    }
    __syncthreads();
    float* red = sm;
    if (tid < 32) red[tid] = 0.f;
    __syncthreads();
    if (actC) {
        atomicAdd(&red[oC], sum);
        atomicAdd(&red[16 + oC], sq);
    }
    __syncthreads();
    if (tid < 16)       atomicAdd(&g_chsum[o_base + tid], red[tid]);
    else if (tid < 32)  atomicAdd(&g_chsq[o_base + tid - 16], red[tid]);
}

// ---------------- K4: BN + residual + ReLU ----------------------------------------
__global__ void bn_kernel(const float* __restrict__ x,
                          const float* __restrict__ gamma, const float* __restrict__ beta,
                          float* __restrict__ out) {
    int bx = blockIdx.x;
    int n = bx >> 7, o = bx & 127;
    int tid = threadIdx.x;
    float mu  = g_chsum[o] * (1.0f / YCNT);
    float var = g_chsq[o] * (1.0f / YCNT) - mu * mu;
    float r = rsqrtf(var + EPS_);
    float gam = gamma[o] * r;
    float bet = beta[o] - mu * gam;
    const float* xb = x + (((size_t)(n * C_ + o)) * T_) * V_;
    const float* yb = g_y + ((size_t)(n * O_ + o)) * T_ * 26;
    float* ob = out + (((size_t)(n * O_ + o)) * T_) * V_;
#pragma unroll
    for (int i = 0; i < 25; i++) {
        int e = tid + i * 512;
        int t = (int)(((unsigned)e * 5243u) >> 17);
        float yv = yb[e + t];
        float val = yv * gam + bet + xb[e];
        ob[e] = fmaxf(val, 0.f);
    }
}

// ---------------- launcher ----------------------------------------------------------
extern "C" void kernel_launch(void* const* d_in, const int* in_sizes, int n_in,
                              void* d_out, int out_size) {
    const float* x     = (const float*)d_in[0];
    const float* Wq    = (const float*)d_in[1];
    const float* bq    = (const float*)d_in[2];
    const float* Wk    = (const float*)d_in[3];
    const float* bk    = (const float*)d_in[4];
    const float* Wv    = (const float*)d_in[5];
    const float* bv    = (const float*)d_in[6];
    const float* Wr    = (const float*)d_in[7];
    const float* br    = (const float*)d_in[8];
    const float* gamma = (const float*)d_in[9];
    const float* beta  = (const float*)d_in[10];
    float* out = (float*)d_out;

    const int smem_bytes = SM_TOT * 4;   // 82432
    cudaFuncSetAttribute(attn_kernel, cudaFuncAttributeMaxDynamicSharedMemorySize, smem_bytes);

    prep_kernel<<<128, 128>>>(Wv);                              // 1 (zero vsum/stats, Wv^T)
    qkv_kernel<<<N_ * T_, 128>>>(x, Wq, bq, Wk, bk, bv);        // 2 (q,k,v + vsum atomics)
    sv_kernel<<<512, 512>>>();                                  // 3 (S precompute)
    attn_kernel<<<1024, 512, smem_bytes>>>(Wr, br);             // 4  <- profiled
    bn_kernel<<<512, 512>>>(x, gamma, beta, out);               // 5
}

// round 15
// speedup vs baseline: 1.2100x; 1.2100x over previous
#include <cuda_runtime.h>

#define N_ 4
#define C_ 128
#define T_ 512
#define V_ 25
#define H_ 16
#define O_ 128
#define EPS_ 1e-5f
#define YCNT 51200.0f   // N*T*V

typedef unsigned long long ull;

// ---------------- scratch ----------------------------------------------------
__device__ float g_q[N_ * T_ * H_];              // [n][t][h]
__device__ float g_k[N_ * T_ * H_];              // [n][t][h]
__device__ float g_wvt[C_ * O_];                 // [c][o]
__device__ float g_v[N_ * T_ * O_ * 32];         // [n][t][o][32]
__device__ float g_vsum[N_ * O_ * 32];           // [n][o][32]
__device__ float g_s[(size_t)N_ * 32 * 64 * 2048]; // [n][gt][c64][g16][tt8][h16] = 64MB
__device__ float g_y[(size_t)N_ * O_ * T_ * 26]; // [n][o][g][26]
__device__ float g_chsum[O_];
__device__ float g_chsq[O_];

// ---------------- helpers -----------------------------------------------------
__device__ __forceinline__ ull ffma2(ull a, ull b, ull c) {
    ull d; asm("fma.rn.f32x2 %0, %1, %2, %3;" : "=l"(d) : "l"(a), "l"(b), "l"(c)); return d;
}
__device__ __forceinline__ ull fmul2(ull a, ull b) {
    ull d; asm("mul.rn.f32x2 %0, %1, %2;" : "=l"(d) : "l"(a), "l"(b)); return d;
}
__device__ __forceinline__ ull fadd2(ull a, ull b) {
    ull d; asm("add.rn.f32x2 %0, %1, %2;" : "=l"(d) : "l"(a), "l"(b)); return d;
}
__device__ __forceinline__ ull dup2(float x) {
    ull d; asm("mov.b64 %0, {%1, %1};" : "=l"(d) : "f"(x)); return d;
}
__device__ __forceinline__ float2 unpack2(ull a) {
    float2 r; asm("mov.b64 {%0, %1}, %2;" : "=f"(r.x), "=f"(r.y) : "l"(a)); return r;
}
__device__ __forceinline__ float tanh_fast(float x) {
    float r; asm("tanh.approx.f32 %0, %1;" : "=f"(r) : "f"(x)); return r;
}
__device__ __forceinline__ void cp16(float* dst, const float* src) {
    unsigned du = (unsigned)__cvta_generic_to_shared(dst);
    asm volatile("cp.async.cg.shared.global [%0], [%1], 16;" :: "r"(du), "l"(src));
}
#define CP_COMMIT() asm volatile("cp.async.commit_group;")
#define CP_WAIT1()  asm volatile("cp.async.wait_group 1;")
#define CP_WAIT2()  asm volatile("cp.async.wait_group 2;")

// ---------------- K0: prep (zero BN accumulators, transpose Wv) ----------------
__global__ void prep_kernel(const float* __restrict__ Wv) {
    int b = blockIdx.x, tid = threadIdx.x;
    int i = b * 128 + tid;          // 0..16383
    int o = i >> 7, c = i & 127;
    g_wvt[c * O_ + o] = Wv[i];
    if (b == 0) { g_chsum[tid] = 0.f; g_chsq[tid] = 0.f; }
}

// ---------------- K1: fused x-load -> xm -> q,k -> v ---------------------------
__global__ void qkv_kernel(const float* __restrict__ x,
                           const float* __restrict__ Wq, const float* __restrict__ bq,
                           const float* __restrict__ Wk, const float* __restrict__ bk,
                           const float* __restrict__ bv) {
    __shared__ float xs[C_][28];
    __shared__ float xm[C_];
    int b = blockIdx.x; int n = b >> 9; int t = b & 511;
    int o = threadIdx.x;
    {
        const float* xp = x + ((n * C_ + o) * T_ + t) * V_;
        float s = 0.f;
#pragma unroll
        for (int v = 0; v < V_; v++) { float xv = xp[v]; xs[o][v] = xv; s += xv; }
        xs[o][25] = 0.f; xs[o][26] = 0.f; xs[o][27] = 0.f;
        xm[o] = s * (1.0f / 25.0f);
    }
    __syncthreads();

    if (o < 32) {
        int h = o & 15;
        bool isQ = o < 16;
        const float* W = isQ ? Wq : Wk;
        float acc = isQ ? bq[h] : bk[h];
#pragma unroll 8
        for (int cc = 0; cc < C_; cc++) acc += W[h * C_ + cc] * xm[cc];
        float* dst = isQ ? g_q : g_k;
        dst[(n * T_ + t) * H_ + h] = acc;
    }

    ull acc[13];
    ull binit = dup2(bv[o]);
#pragma unroll
    for (int j = 0; j < 13; j++) acc[j] = binit;
    for (int c = 0; c < C_; c++) {
        ull wd = dup2(g_wvt[c * O_ + o]);
        const ulonglong2* xr = (const ulonglong2*)xs[c];
#pragma unroll
        for (int j = 0; j < 6; j++) {
            ulonglong2 p = xr[j];
            acc[2 * j]     = ffma2(wd, p.x, acc[2 * j]);
            acc[2 * j + 1] = ffma2(wd, p.y, acc[2 * j + 1]);
        }
        acc[12] = ffma2(wd, *((const ull*)xs[c] + 12), acc[12]);
    }
    float* row = g_v + (((size_t)(n * T_ + t)) * O_ + o) * 32;
#pragma unroll
    for (int j = 0; j < 12; j++) {
        float2 u = unpack2(acc[j]);
        row[2 * j] = u.x; row[2 * j + 1] = u.y;
    }
    { float2 u = unpack2(acc[12]); row[24] = u.x; }
#pragma unroll
    for (int p = 25; p < 32; p++) row[p] = 0.f;
}

// ---------------- K2: sv_kernel — S precompute (0-511) + direct vsum (512-1023) --
__global__ void __launch_bounds__(512)
sv_kernel() {
    __shared__ float red[16][33];
    int b = blockIdx.x;
    int tid = threadIdx.x;
    if (b < 512) {
        // S part: block = (n4, gt32, cq4); 16 chunks each. thread = (g, tt, h-quad)
        int n = b >> 7, gt = (b >> 2) & 31, cq = b & 3;
        int g = tid >> 5, tt = (tid >> 2) & 7, hq = tid & 3;
        float4 q4 = *(const float4*)(g_q + (n * T_ + gt * 16 + g) * H_ + hq * 4);
        float* sbase = g_s + ((size_t)(n * 32 + gt)) * 64 * 2048 + tid * 4;
#pragma unroll 4
        for (int cc = cq * 16; cc < cq * 16 + 16; cc++) {
            float4 k4 = *(const float4*)(g_k + (n * T_ + cc * 8 + tt) * H_ + hq * 4);
            float4 s;
            s.x = tanh_fast(q4.x - k4.x);
            s.y = tanh_fast(q4.y - k4.y);
            s.z = tanh_fast(q4.z - k4.z);
            s.w = tanh_fast(q4.w - k4.w);
            *(float4*)(sbase + (size_t)cc * 2048) = s;
        }
    } else {
        // vsum part: block = (n, o); direct write, no atomics
        int b2 = b - 512;
        int n = b2 >> 7, o = b2 & 127;
        int tsub = tid >> 5, comp = tid & 31;
        const float* base = g_v + (((size_t)(n * T_ + tsub * 32)) * O_ + o) * 32 + comp;
        float a0 = 0.f, a1 = 0.f, a2 = 0.f, a3 = 0.f;
#pragma unroll
        for (int u = 0; u < 32; u += 4) {
            a0 += base[(size_t)(u + 0) * O_ * 32];
            a1 += base[(size_t)(u + 1) * O_ * 32];
            a2 += base[(size_t)(u + 2) * O_ * 32];
            a3 += base[(size_t)(u + 3) * O_ * 32];
        }
        red[tsub][comp] = (a0 + a1) + (a2 + a3);
        __syncthreads();
        if (tid < 32) {
            float s = 0.f;
#pragma unroll
            for (int r = 0; r < 16; r++) s += red[r][tid];
            g_vsum[(n * O_ + o) * 32 + tid] = s;
        }
    }
}

// ---------------- K3: fused attention — cp.async S pipeline (R13 config) --------
#define TCH 8
#define NCHUNK (T_ / TCH)            // 64
#define SCH 2048                     // S chunk floats (16g x 8tt x 16h)
#define AROWP 132
#define ABUF (16 * AROWP)            // 2112
#define SM_AS (3 * SCH)              // 6144
#define SM_TOT (SM_AS + 2 * ABUF)    // 10368 floats = 41472 B

// B stage: 4 g per thread; S rows stride 128 (unpadded)
__device__ __forceinline__ void b_stage4(const float* __restrict__ Sb, float* __restrict__ Ab,
                                         const ull* __restrict__ w, int oB, int ttB, int gq) {
    float outv[4];
    const float* srow = Sb + ttB * 16;
#pragma unroll
    for (int i = 0; i < 4; i++) {
        int g = gq * 4 + i;
        const ulonglong2* sp = (const ulonglong2*)(srow + g * 128);
        ulonglong2 s0 = sp[0], s1 = sp[1];
        ull a0 = fmul2(w[0], s0.x);  a0 = ffma2(w[1], s0.y, a0);
        a0 = ffma2(w[2], s1.x, a0);  a0 = ffma2(w[3], s1.y, a0);
        ulonglong2 s2 = sp[2], s3 = sp[3];
        ull a1 = fmul2(w[4], s2.x);  a1 = ffma2(w[5], s2.y, a1);
        a1 = ffma2(w[6], s3.x, a1);  a1 = ffma2(w[7], s3.y, a1);
        float2 u = unpack2(fadd2(a0, a1));
        outv[i] = u.x + u.y;
    }
    *(float4*)(Ab + oB * AROWP + ttB * 16 + gq * 4) =
        make_float4(outv[0], outv[1], outv[2], outv[3]);
}

// C stage: scalar v, acc = 8 f32x2 pairs over g
__device__ __forceinline__ void c_scalar(const float* __restrict__ Ab, int oC,
                                         const float* __restrict__ vc, ull* __restrict__ acc) {
    const float* arow = Ab + oC * AROWP;
#pragma unroll
    for (int tt = 0; tt < TCH; tt++) {
        const ulonglong2* ap = (const ulonglong2*)(arow + tt * 16);
        ull d = dup2(vc[tt]);
        ulonglong2 p0 = ap[0], p1 = ap[1];
        acc[0] = ffma2(p0.x, d, acc[0]);
        acc[1] = ffma2(p0.y, d, acc[1]);
        acc[2] = ffma2(p1.x, d, acc[2]);
        acc[3] = ffma2(p1.y, d, acc[3]);
        ulonglong2 p2 = ap[2], p3 = ap[3];
        acc[4] = ffma2(p2.x, d, acc[4]);
        acc[5] = ffma2(p2.y, d, acc[5]);
        acc[6] = ffma2(p3.x, d, acc[6]);
        acc[7] = ffma2(p3.y, d, acc[7]);
    }
}

__global__ void __launch_bounds__(512, 2)
attn_kernel(const float* __restrict__ Wr, const float* __restrict__ br) {
    extern __shared__ float sm[];
    float* S_s = sm;                 // 3 x 2048
    float* A_s = sm + SM_AS;         // 2 x 2112

    int bx = blockIdx.x;
    int gt = bx & 31, ot = (bx >> 5) & 7, n = bx >> 8;
    int o_base = ot * 16, g_base = gt * 16;
    int tid = threadIdx.x;

    // roles
    int oB = tid & 15, ttB = (tid >> 4) & 7, gq = tid >> 7;    // B: 4 g each
    int oC = tid / 26, vC = tid - oC * 26;                     // C: scalar v (tid<416)
    bool actC = tid < 416;

    const float* sg = g_s + ((size_t)(n * 32 + gt)) * 64 * SCH + tid * 4;
    float* sd = S_s + tid * 4;

    ull w[8];
    {
        const ull* wp = (const ull*)(Wr + (o_base + oB) * H_);
#pragma unroll
        for (int j = 0; j < 8; j++) w[j] = wp[j];
    }

    ull acc[8];
    float vcur[8];
    const float* vbase = actC
        ? g_v + (((size_t)n * T_) * O_ + o_base + oC) * 32 + vC
        : g_v;
    if (actC) {
        float brv = br[o_base + oC];
        float vs = g_vsum[(n * O_ + o_base + oC) * 32 + vC];
        ull i0 = dup2(brv * vs);
#pragma unroll
        for (int p = 0; p < 8; p++) acc[p] = i0;
#pragma unroll
        for (int tt = 0; tt < TCH; tt++)
            vcur[tt] = vbase[(size_t)tt * O_ * 32];
    }

    // prologue: issue S0, S1, S2 as separate groups
    cp16(sd + 0 * SCH, sg + (size_t)0 * SCH); CP_COMMIT();
    cp16(sd + 1 * SCH, sg + (size_t)1 * SCH); CP_COMMIT();
    cp16(sd + 2 * SCH, sg + (size_t)2 * SCH); CP_COMMIT();
    CP_WAIT2();            // own S0 done (pending: S1,S2)
    __syncthreads();       // all S0 done
    b_stage4(S_s, A_s, w, oB, ttB, gq);      // A(0) -> buf0
    CP_WAIT1();            // own S1 done (pending: S2)
    __syncthreads();       // all S1 done + A0 visible

    // main loop: invariant at chunk c: S(c+1) all-done, A(c) visible, pending={S(c+2)}
    int sb = 0;            // buffer index = c % 3 (target of S(c+3))
    for (int c = 0; c < NCHUNK; c++) {
        int ab = c & 1;
        if (c + 3 < NCHUNK)
            cp16(sd + sb * SCH, sg + (size_t)(c + 3) * SCH);
        CP_COMMIT();       // uniform group count (empty group near tail)
        int rb = sb + 1; if (rb == 3) rb = 0;   // (c+1) % 3
        if (c + 1 < NCHUNK)
            b_stage4(S_s + rb * SCH, A_s + (ab ^ 1) * ABUF, w, oB, ttB, gq);
        if (actC) {
            c_scalar(A_s + ab * ABUF, oC, vcur, acc);
            if (c + 1 < NCHUNK) {
                const float* vb2 = vbase + (size_t)(c + 1) * TCH * O_ * 32;
#pragma unroll
                for (int tt = 0; tt < TCH; tt++)
                    vcur[tt] = vb2[(size_t)tt * O_ * 32];
            }
        }
        CP_WAIT1();        // own S(c+2) done
        __syncthreads();   // all S(c+2) done + A(c+1) visible
        sb = rb;
    }

    // ---- epilogue: y writes + BN partial stats ----
    float sum = 0.f, sq = 0.f;
    if (actC) {
        int o0 = o_base + oC;
        float* ybase = g_y + (((size_t)(n * O_ + o0)) * T_ + g_base) * 26 + vC;
#pragma unroll
        for (int p = 0; p < 8; p++) {
            float2 u = unpack2(acc[p]);
            ybase[(2 * p) * 26]     = u.x;
            ybase[(2 * p + 1) * 26] = u.y;
            sum += u.x + u.y;
            sq  += u.x * u.x + u.y * u.y;
        }
    }
    __syncthreads();
    float* red = sm;
    if (tid < 32) red[tid] = 0.f;
    __syncthreads();
    if (actC) {
        atomicAdd(&red[oC], sum);
        atomicAdd(&red[16 + oC], sq);
    }
    __syncthreads();
    if (tid < 16)       atomicAdd(&g_chsum[o_base + tid], red[tid]);
    else if (tid < 32)  atomicAdd(&g_chsq[o_base + tid - 16], red[tid]);
}

// ---------------- K4: BN + residual + ReLU ----------------------------------------
__global__ void bn_kernel(const float* __restrict__ x,
                          const float* __restrict__ gamma, const float* __restrict__ beta,
                          float* __restrict__ out) {
    int bx = blockIdx.x;
    int n = bx >> 7, o = bx & 127;
    int tid = threadIdx.x;
    float mu  = g_chsum[o] * (1.0f / YCNT);
    float var = g_chsq[o] * (1.0f / YCNT) - mu * mu;
    float r = rsqrtf(var + EPS_);
    float gam = gamma[o] * r;
    float bet = beta[o] - mu * gam;
    const float* xb = x + (((size_t)(n * C_ + o)) * T_) * V_;
    const float* yb = g_y + ((size_t)(n * O_ + o)) * T_ * 26;
    float* ob = out + (((size_t)(n * O_ + o)) * T_) * V_;
#pragma unroll
    for (int i = 0; i < 25; i++) {
        int e = tid + i * 512;
        int t = (int)(((unsigned)e * 5243u) >> 17);
        float yv = yb[e + t];
        float val = yv * gam + bet + xb[e];
        ob[e] = fmaxf(val, 0.f);
    }
}

// ---------------- launcher ----------------------------------------------------------
extern "C" void kernel_launch(void* const* d_in, const int* in_sizes, int n_in,
                              void* d_out, int out_size) {
    const float* x     = (const float*)d_in[0];
    const float* Wq    = (const float*)d_in[1];
    const float* bq    = (const float*)d_in[2];
    const float* Wk    = (const float*)d_in[3];
    const float* bk    = (const float*)d_in[4];
    const float* Wv    = (const float*)d_in[5];
    const float* bv    = (const float*)d_in[6];
    const float* Wr    = (const float*)d_in[7];
    const float* br    = (const float*)d_in[8];
    const float* gamma = (const float*)d_in[9];
    const float* beta  = (const float*)d_in[10];
    float* out = (float*)d_out;

    const int smem_bytes = SM_TOT * 4;   // 41472
    cudaFuncSetAttribute(attn_kernel, cudaFuncAttributeMaxDynamicSharedMemorySize, smem_bytes);

    prep_kernel<<<128, 128>>>(Wv);                              // 1
    qkv_kernel<<<N_ * T_, 128>>>(x, Wq, bq, Wk, bk, bv);        // 2 (no atomics)
    sv_kernel<<<1024, 512>>>();                                 // 3 (S + direct vsum)
    attn_kernel<<<1024, 512, smem_bytes>>>(Wr, br);             // 4  <- profiled
    bn_kernel<<<512, 512>>>(x, gamma, beta, out);               // 5
}

// round 16
// speedup vs baseline: 1.2964x; 1.0714x over previous
#include <cuda_runtime.h>

#define N_ 4
#define C_ 128
#define T_ 512
#define V_ 25
#define H_ 16
#define O_ 128
#define EPS_ 1e-5f
#define YCNT 51200.0f   // N*T*V

typedef unsigned long long ull;

// ---------------- scratch ----------------------------------------------------
__device__ float g_q[N_ * T_ * H_];              // [n][t][h]
__device__ float g_k[N_ * T_ * H_];              // [n][t][h]
__device__ float g_wvt[C_ * O_];                 // [c][o]
__device__ float g_v[N_ * T_ * O_ * 32];         // [n][t][o][32]
__device__ float g_vsum[N_ * O_ * 32];           // [n][o][32]
__device__ float g_s[(size_t)N_ * 32 * 64 * 2048]; // [n][gt][c64][g16][tt8][h16] = 64MB
__device__ float g_y[(size_t)N_ * O_ * T_ * 26]; // [n][o][g][26]
__device__ float g_chsum[O_];
__device__ float g_chsq[O_];

// ---------------- helpers -----------------------------------------------------
__device__ __forceinline__ ull ffma2(ull a, ull b, ull c) {
    ull d; asm("fma.rn.f32x2 %0, %1, %2, %3;" : "=l"(d) : "l"(a), "l"(b), "l"(c)); return d;
}
__device__ __forceinline__ ull fmul2(ull a, ull b) {
    ull d; asm("mul.rn.f32x2 %0, %1, %2;" : "=l"(d) : "l"(a), "l"(b)); return d;
}
__device__ __forceinline__ ull fadd2(ull a, ull b) {
    ull d; asm("add.rn.f32x2 %0, %1, %2;" : "=l"(d) : "l"(a), "l"(b)); return d;
}
__device__ __forceinline__ ull dup2(float x) {
    ull d; asm("mov.b64 %0, {%1, %1};" : "=l"(d) : "f"(x)); return d;
}
__device__ __forceinline__ ull pack2(float x, float y) {
    ull d; asm("mov.b64 %0, {%1, %2};" : "=l"(d) : "f"(x), "f"(y)); return d;
}
__device__ __forceinline__ float2 unpack2(ull a) {
    float2 r; asm("mov.b64 {%0, %1}, %2;" : "=f"(r.x), "=f"(r.y) : "l"(a)); return r;
}
__device__ __forceinline__ float tanh_fast(float x) {
    float r; asm("tanh.approx.f32 %0, %1;" : "=f"(r) : "f"(x)); return r;
}
__device__ __forceinline__ void cp16(float* dst, const float* src) {
    unsigned du = (unsigned)__cvta_generic_to_shared(dst);
    asm volatile("cp.async.cg.shared.global [%0], [%1], 16;" :: "r"(du), "l"(src));
}
#define CP_COMMIT() asm volatile("cp.async.commit_group;")
#define CP_WAIT1()  asm volatile("cp.async.wait_group 1;")
#define CP_WAIT2()  asm volatile("cp.async.wait_group 2;")

// ---------------- K0: prep (zero BN accumulators, transpose Wv) ----------------
__global__ void prep_kernel(const float* __restrict__ Wv) {
    int b = blockIdx.x, tid = threadIdx.x;
    int i = b * 128 + tid;
    int o = i >> 7, c = i & 127;
    g_wvt[c * O_ + o] = Wv[i];
    if (b == 0) { g_chsum[tid] = 0.f; g_chsq[tid] = 0.f; }
}

// ---------------- K1: fused x-load -> xm -> q,k -> v (coalesced x load) --------
__global__ void qkv_kernel(const float* __restrict__ x,
                           const float* __restrict__ Wq, const float* __restrict__ bq,
                           const float* __restrict__ Wk, const float* __restrict__ bk,
                           const float* __restrict__ bv) {
    __shared__ float xs[C_][28];
    __shared__ float xm[C_];
    int b = blockIdx.x; int n = b >> 9; int t = b & 511;
    int tid = threadIdx.x;
    // cooperative, mostly-coalesced load of x[n,:,t,:]
    {
        const float* xbase = x + ((size_t)n * C_ * T_ + t) * V_;
        for (int i = tid; i < C_ * V_; i += 128) {
            int c = (int)(((unsigned)i * 5243u) >> 17);   // i/25 (valid i<12800)
            int v = i - c * 25;
            xs[c][v] = xbase[(size_t)c * T_ * V_ + v];
        }
        xs[tid][25] = 0.f; xs[tid][26] = 0.f; xs[tid][27] = 0.f;
    }
    __syncthreads();
    int o = tid;
    {
        float s = 0.f;
#pragma unroll
        for (int v = 0; v < V_; v++) s += xs[o][v];
        xm[o] = s * (1.0f / 25.0f);
    }
    __syncthreads();

    if (o < 32) {
        int h = o & 15;
        bool isQ = o < 16;
        const float* W = isQ ? Wq : Wk;
        float acc = isQ ? bq[h] : bk[h];
#pragma unroll 8
        for (int cc = 0; cc < C_; cc++) acc += W[h * C_ + cc] * xm[cc];
        float* dst = isQ ? g_q : g_k;
        dst[(n * T_ + t) * H_ + h] = acc;
    }

    ull acc[13];
    ull binit = dup2(bv[o]);
#pragma unroll
    for (int j = 0; j < 13; j++) acc[j] = binit;
    for (int c = 0; c < C_; c++) {
        ull wd = dup2(g_wvt[c * O_ + o]);
        const ulonglong2* xr = (const ulonglong2*)xs[c];
#pragma unroll
        for (int j = 0; j < 6; j++) {
            ulonglong2 p = xr[j];
            acc[2 * j]     = ffma2(wd, p.x, acc[2 * j]);
            acc[2 * j + 1] = ffma2(wd, p.y, acc[2 * j + 1]);
        }
        acc[12] = ffma2(wd, *((const ull*)xs[c] + 12), acc[12]);
    }
    float* row = g_v + (((size_t)(n * T_ + t)) * O_ + o) * 32;
#pragma unroll
    for (int j = 0; j < 12; j++) {
        float2 u = unpack2(acc[j]);
        row[2 * j] = u.x; row[2 * j + 1] = u.y;
    }
    { float2 u = unpack2(acc[12]); row[24] = u.x; }
#pragma unroll
    for (int p = 25; p < 32; p++) row[p] = 0.f;
}

// ---------------- K2: sv_kernel — S precompute (0-511) + direct vsum (512-1023) --
__global__ void __launch_bounds__(512)
sv_kernel() {
    __shared__ float red[16][33];
    int b = blockIdx.x;
    int tid = threadIdx.x;
    if (b < 512) {
        int n = b >> 7, gt = (b >> 2) & 31, cq = b & 3;
        int g = tid >> 5, tt = (tid >> 2) & 7, hq = tid & 3;
        float4 q4 = *(const float4*)(g_q + (n * T_ + gt * 16 + g) * H_ + hq * 4);
        float* sbase = g_s + ((size_t)(n * 32 + gt)) * 64 * 2048 + tid * 4;
#pragma unroll 4
        for (int cc = cq * 16; cc < cq * 16 + 16; cc++) {
            float4 k4 = *(const float4*)(g_k + (n * T_ + cc * 8 + tt) * H_ + hq * 4);
            float4 s;
            s.x = tanh_fast(q4.x - k4.x);
            s.y = tanh_fast(q4.y - k4.y);
            s.z = tanh_fast(q4.z - k4.z);
            s.w = tanh_fast(q4.w - k4.w);
            *(float4*)(sbase + (size_t)cc * 2048) = s;
        }
    } else {
        int b2 = b - 512;
        int n = b2 >> 7, o = b2 & 127;
        int tsub = tid >> 5, comp = tid & 31;
        const float* base = g_v + (((size_t)(n * T_ + tsub * 32)) * O_ + o) * 32 + comp;
        float a0 = 0.f, a1 = 0.f, a2 = 0.f, a3 = 0.f;
#pragma unroll
        for (int u = 0; u < 32; u += 4) {
            a0 += base[(size_t)(u + 0) * O_ * 32];
            a1 += base[(size_t)(u + 1) * O_ * 32];
            a2 += base[(size_t)(u + 2) * O_ * 32];
            a3 += base[(size_t)(u + 3) * O_ * 32];
        }
        red[tsub][comp] = (a0 + a1) + (a2 + a3);
        __syncthreads();
        if (tid < 32) {
            float s = 0.f;
#pragma unroll
            for (int r = 0; r < 16; r++) s += red[r][tid];
            g_vsum[(n * O_ + o) * 32 + tid] = s;
        }
    }
}

// ---------------- K3: fused attention — warp-specialized B/C roles --------------
#define TCH 8
#define NCHUNK (T_ / TCH)            // 64
#define SCH 2048
#define AROWP 132
#define ABUF (16 * AROWP)            // 2112
#define SM_AS (3 * SCH)              // 6144
#define SM_TOT (SM_AS + 2 * ABUF)    // 10368 floats = 41472 B

// B stage: 2 o (oP, oP+8) x 4 g per thread
__device__ __forceinline__ void b_stage2o(const float* __restrict__ Sb, float* __restrict__ Ab,
                                          const ull* __restrict__ w0, const ull* __restrict__ w1,
                                          int oP, int ttB, int gq) {
    float out0[4], out1[4];
    const float* srow = Sb + ttB * 16;
#pragma unroll
    for (int i = 0; i < 4; i++) {
        int g = gq * 4 + i;
        const ulonglong2* sp = (const ulonglong2*)(srow + g * 128);
        ulonglong2 s0 = sp[0], s1 = sp[1];
        ulonglong2 s2 = sp[2], s3 = sp[3];
        ull a0 = fmul2(w0[0], s0.x);  a0 = ffma2(w0[1], s0.y, a0);
        a0 = ffma2(w0[2], s1.x, a0);  a0 = ffma2(w0[3], s1.y, a0);
        ull a1 = fmul2(w0[4], s2.x);  a1 = ffma2(w0[5], s2.y, a1);
        a1 = ffma2(w0[6], s3.x, a1);  a1 = ffma2(w0[7], s3.y, a1);
        float2 u = unpack2(fadd2(a0, a1));
        out0[i] = u.x + u.y;
        ull b0 = fmul2(w1[0], s0.x);  b0 = ffma2(w1[1], s0.y, b0);
        b0 = ffma2(w1[2], s1.x, b0);  b0 = ffma2(w1[3], s1.y, b0);
        ull b1 = fmul2(w1[4], s2.x);  b1 = ffma2(w1[5], s2.y, b1);
        b1 = ffma2(w1[6], s3.x, b1);  b1 = ffma2(w1[7], s3.y, b1);
        float2 v = unpack2(fadd2(b0, b1));
        out1[i] = v.x + v.y;
    }
    *(float4*)(Ab + oP * AROWP + ttB * 16 + gq * 4) =
        make_float4(out0[0], out0[1], out0[2], out0[3]);
    *(float4*)(Ab + (oP + 8) * AROWP + ttB * 16 + gq * 4) =
        make_float4(out1[0], out1[1], out1[2], out1[3]);
}

__global__ void __launch_bounds__(512, 2)
attn_kernel(const float* __restrict__ Wr, const float* __restrict__ br) {
    extern __shared__ float sm[];
    float* S_s = sm;                 // 3 x 2048
    float* A_s = sm + SM_AS;         // 2 x 2112

    int bx = blockIdx.x;
    int gt = bx & 31, ot = (bx >> 5) & 7, n = bx >> 8;
    int o_base = ot * 16, g_base = gt * 16;
    int tid = threadIdx.x;

    float sum = 0.f, sq = 0.f;       // filled by C role
    ull acc0[8], acc1[8];            // used by C role only

    if (tid < 256) {
        // ================= B role: build A = Wr . S, feed S via cp.async =======
        int oP = tid & 7, ttB = (tid >> 3) & 7, gq = tid >> 6;
        ull w0[8], w1[8];
        {
            const ull* wp0 = (const ull*)(Wr + (o_base + oP) * H_);
            const ull* wp1 = (const ull*)(Wr + (o_base + oP + 8) * H_);
#pragma unroll
            for (int j = 0; j < 8; j++) { w0[j] = wp0[j]; w1[j] = wp1[j]; }
        }
        const float* sgb = g_s + ((size_t)(n * 32 + gt)) * 64 * SCH + tid * 8;
        float* sdb = S_s + tid * 8;

        // prologue: S0,S1,S2 as separate groups (2 cp16 per thread per chunk)
        cp16(sdb + 0 * SCH, sgb + (size_t)0 * SCH);
        cp16(sdb + 0 * SCH + 4, sgb + (size_t)0 * SCH + 4);
        CP_COMMIT();
        cp16(sdb + 1 * SCH, sgb + (size_t)1 * SCH);
        cp16(sdb + 1 * SCH + 4, sgb + (size_t)1 * SCH + 4);
        CP_COMMIT();
        cp16(sdb + 2 * SCH, sgb + (size_t)2 * SCH);
        cp16(sdb + 2 * SCH + 4, sgb + (size_t)2 * SCH + 4);
        CP_COMMIT();
        CP_WAIT2();
        __syncthreads();                         // bar 1: S0 ready
        b_stage2o(S_s, A_s, w0, w1, oP, ttB, gq);   // A(0)
        CP_WAIT1();
        __syncthreads();                         // bar 2: S1 ready + A0 visible

        int sb = 0;
        for (int c = 0; c < NCHUNK; c++) {
            if (c + 3 < NCHUNK) {
                cp16(sdb + sb * SCH, sgb + (size_t)(c + 3) * SCH);
                cp16(sdb + sb * SCH + 4, sgb + (size_t)(c + 3) * SCH + 4);
            }
            CP_COMMIT();
            int rb = sb + 1; if (rb == 3) rb = 0;
            if (c + 1 < NCHUNK)
                b_stage2o(S_s + rb * SCH, A_s + ((c + 1) & 1) * ABUF, w0, w1, oP, ttB, gq);
            CP_WAIT1();
            __syncthreads();                     // bars 3..66
            sb = rb;
        }
    } else {
        // ================= C role: y += A * v ===================================
        int ct = tid - 256;
        int oC = ct / 13, jC = ct - oC * 13;
        bool actC = ct < 208;
        if (!actC) { oC = 0; jC = 0; }
        const float* vbase = g_v + (((size_t)n * T_) * O_ + o_base + oC) * 32 + 2 * jC;
        ull vcur[4];
        if (actC) {
            float brv = br[o_base + oC];
            const float* vs = g_vsum + (n * O_ + o_base + oC) * 32 + 2 * jC;
            ull i0 = dup2(brv * vs[0]);
            ull i1 = dup2(brv * vs[1]);
#pragma unroll
            for (int p = 0; p < 8; p++) { acc0[p] = i0; acc1[p] = i1; }
#pragma unroll
            for (int tt = 0; tt < 4; tt++)
                vcur[tt] = *(const ull*)(vbase + (size_t)tt * O_ * 32);
        }
        __syncthreads();                         // bar 1
        __syncthreads();                         // bar 2

        for (int c = 0; c < NCHUNK; c++) {
            if (actC) {
                const float* arow = A_s + (c & 1) * ABUF + oC * AROWP;
#pragma unroll
                for (int half = 0; half < 2; half++) {
#pragma unroll
                    for (int tt = 0; tt < 4; tt++) {
                        const ulonglong2* ap =
                            (const ulonglong2*)(arow + (half * 4 + tt) * 16);
                        ulonglong2 p0 = ap[0], p1 = ap[1];
                        ulonglong2 p2 = ap[2], p3 = ap[3];
                        float2 vv = unpack2(vcur[tt]);
                        ull d0 = dup2(vv.x), d1 = dup2(vv.y);
                        acc0[0] = ffma2(p0.x, d0, acc0[0]);
                        acc0[1] = ffma2(p0.y, d0, acc0[1]);
                        acc0[2] = ffma2(p1.x, d0, acc0[2]);
                        acc0[3] = ffma2(p1.y, d0, acc0[3]);
                        acc0[4] = ffma2(p2.x, d0, acc0[4]);
                        acc0[5] = ffma2(p2.y, d0, acc0[5]);
                        acc0[6] = ffma2(p3.x, d0, acc0[6]);
                        acc0[7] = ffma2(p3.y, d0, acc0[7]);
                        acc1[0] = ffma2(p0.x, d1, acc1[0]);
                        acc1[1] = ffma2(p0.y, d1, acc1[1]);
                        acc1[2] = ffma2(p1.x, d1, acc1[2]);
                        acc1[3] = ffma2(p1.y, d1, acc1[3]);
                        acc1[4] = ffma2(p2.x, d1, acc1[4]);
                        acc1[5] = ffma2(p2.y, d1, acc1[5]);
                        acc1[6] = ffma2(p3.x, d1, acc1[6]);
                        acc1[7] = ffma2(p3.y, d1, acc1[7]);
                    }
                    // reload vcur: second half of chunk c, then first half of c+1
                    const float* vnx = (half == 0)
                        ? vbase + ((size_t)c * TCH + 4) * O_ * 32
                        : vbase + ((size_t)(c + 1) * TCH) * O_ * 32;
                    if (half == 0 || c + 1 < NCHUNK) {
#pragma unroll
                        for (int tt = 0; tt < 4; tt++)
                            vcur[tt] = *(const ull*)(vnx + (size_t)tt * O_ * 32);
                    }
                }
            }
            __syncthreads();                     // bars 3..66
        }

        // y writes + per-thread BN partials
        if (actC) {
            int o0 = o_base + oC;
            float* ybase = g_y + (((size_t)(n * O_ + o0)) * T_ + g_base) * 26 + 2 * jC;
#pragma unroll
            for (int p = 0; p < 8; p++) {
                float2 u0 = unpack2(acc0[p]);
                float2 u1 = unpack2(acc1[p]);
                *(ull*)(ybase + (2 * p) * 26)     = pack2(u0.x, u1.x);
                *(ull*)(ybase + (2 * p + 1) * 26) = pack2(u0.y, u1.y);
                sum += u0.x + u0.y + u1.x + u1.y;
                sq  += u0.x * u0.x + u0.y * u0.y + u1.x * u1.x + u1.y * u1.y;
            }
        }
    }

    // ---- common epilogue: BN stat reduction ----
    float* red = sm;
    if (tid < 32) red[tid] = 0.f;
    __syncthreads();
    if (tid >= 256 && (tid - 256) < 208) {
        int oC = (tid - 256) / 13;
        atomicAdd(&red[oC], sum);
        atomicAdd(&red[16 + oC], sq);
    }
    __syncthreads();
    if (tid < 16)       atomicAdd(&g_chsum[o_base + tid], red[tid]);
    else if (tid < 32)  atomicAdd(&g_chsq[o_base + tid - 16], red[tid]);
}

// ---------------- K4: BN + residual + ReLU ----------------------------------------
__global__ void bn_kernel(const float* __restrict__ x,
                          const float* __restrict__ gamma, const float* __restrict__ beta,
                          float* __restrict__ out) {
    int bx = blockIdx.x;
    int n = bx >> 7, o = bx & 127;
    int tid = threadIdx.x;
    float mu  = g_chsum[o] * (1.0f / YCNT);
    float var = g_chsq[o] * (1.0f / YCNT) - mu * mu;
    float r = rsqrtf(var + EPS_);
    float gam = gamma[o] * r;
    float bet = beta[o] - mu * gam;
    const float* xb = x + (((size_t)(n * C_ + o)) * T_) * V_;
    const float* yb = g_y + ((size_t)(n * O_ + o)) * T_ * 26;
    float* ob = out + (((size_t)(n * O_ + o)) * T_) * V_;
#pragma unroll
    for (int i = 0; i < 25; i++) {
        int e = tid + i * 512;
        int t = (int)(((unsigned)e * 5243u) >> 17);
        float yv = yb[e + t];
        float val = yv * gam + bet + xb[e];
        ob[e] = fmaxf(val, 0.f);
    }
}

// ---------------- launcher ----------------------------------------------------------
extern "C" void kernel_launch(void* const* d_in, const int* in_sizes, int n_in,
                              void* d_out, int out_size) {
    const float* x     = (const float*)d_in[0];
    const float* Wq    = (const float*)d_in[1];
    const float* bq    = (const float*)d_in[2];
    const float* Wk    = (const float*)d_in[3];
    const float* bk    = (const float*)d_in[4];
    const float* Wv    = (const float*)d_in[5];
    const float* bv    = (const float*)d_in[6];
    const float* Wr    = (const float*)d_in[7];
    const float* br    = (const float*)d_in[8];
    const float* gamma = (const float*)d_in[9];
    const float* beta  = (const float*)d_in[10];
    float* out = (float*)d_out;

    const int smem_bytes = SM_TOT * 4;   // 41472
    cudaFuncSetAttribute(attn_kernel, cudaFuncAttributeMaxDynamicSharedMemorySize, smem_bytes);

    prep_kernel<<<128, 128>>>(Wv);                              // 1
    qkv_kernel<<<N_ * T_, 128>>>(x, Wq, bq, Wk, bk, bv);        // 2
    sv_kernel<<<1024, 512>>>();                                 // 3
    attn_kernel<<<1024, 512, smem_bytes>>>(Wr, br);             // 4  <- profiled
    bn_kernel<<<512, 512>>>(x, gamma, beta, out);               // 5
}

// round 17
// speedup vs baseline: 1.3062x; 1.0076x over previous
#include <cuda_runtime.h>

#define N_ 4
#define C_ 128
#define T_ 512
#define V_ 25
#define H_ 16
#define O_ 128
#define EPS_ 1e-5f
#define YCNT 51200.0f   // N*T*V

typedef unsigned long long ull;

// ---------------- scratch ----------------------------------------------------
__device__ float g_q[N_ * T_ * H_];              // [n][t][h]
__device__ float g_k[N_ * T_ * H_];              // [n][t][h]
__device__ float g_wvt[C_ * O_];                 // [c][o]
__device__ float g_v[N_ * T_ * O_ * 32];         // [n][t][o][32]
__device__ float g_vsum[N_ * O_ * 32];           // [n][o][32]
__device__ float g_s[(size_t)N_ * 32 * 64 * 2048]; // [n][gt][c64][g16][tt8][h16] = 64MB
__device__ float g_y[(size_t)N_ * O_ * T_ * 26]; // [n][o][g][26]
__device__ float g_chsum[O_];
__device__ float g_chsq[O_];

// ---------------- helpers -----------------------------------------------------
__device__ __forceinline__ ull ffma2(ull a, ull b, ull c) {
    ull d; asm("fma.rn.f32x2 %0, %1, %2, %3;" : "=l"(d) : "l"(a), "l"(b), "l"(c)); return d;
}
__device__ __forceinline__ ull fmul2(ull a, ull b) {
    ull d; asm("mul.rn.f32x2 %0, %1, %2;" : "=l"(d) : "l"(a), "l"(b)); return d;
}
__device__ __forceinline__ ull fadd2(ull a, ull b) {
    ull d; asm("add.rn.f32x2 %0, %1, %2;" : "=l"(d) : "l"(a), "l"(b)); return d;
}
__device__ __forceinline__ ull dup2(float x) {
    ull d; asm("mov.b64 %0, {%1, %1};" : "=l"(d) : "f"(x)); return d;
}
__device__ __forceinline__ ull pack2(float x, float y) {
    ull d; asm("mov.b64 %0, {%1, %2};" : "=l"(d) : "f"(x), "f"(y)); return d;
}
__device__ __forceinline__ float2 unpack2(ull a) {
    float2 r; asm("mov.b64 {%0, %1}, %2;" : "=f"(r.x), "=f"(r.y) : "l"(a)); return r;
}
__device__ __forceinline__ float tanh_fast(float x) {
    float r; asm("tanh.approx.f32 %0, %1;" : "=f"(r) : "f"(x)); return r;
}
__device__ __forceinline__ void cp16(float* dst, const float* src) {
    unsigned du = (unsigned)__cvta_generic_to_shared(dst);
    asm volatile("cp.async.cg.shared.global [%0], [%1], 16;" :: "r"(du), "l"(src));
}
#define CP_COMMIT() asm volatile("cp.async.commit_group;")
#define CP_WAIT1()  asm volatile("cp.async.wait_group 1;")
#define CP_WAIT2()  asm volatile("cp.async.wait_group 2;")

// ---------------- K0: prep (zero BN accumulators, transpose Wv) ----------------
__global__ void prep_kernel(const float* __restrict__ Wv) {
    int b = blockIdx.x, tid = threadIdx.x;
    int i = b * 128 + tid;
    int o = i >> 7, c = i & 127;
    g_wvt[c * O_ + o] = Wv[i];
    if (b == 0) { g_chsum[tid] = 0.f; g_chsq[tid] = 0.f; }
}

// ---------------- K1: fused x-load -> xm -> q,k -> v (coalesced x load) --------
__global__ void qkv_kernel(const float* __restrict__ x,
                           const float* __restrict__ Wq, const float* __restrict__ bq,
                           const float* __restrict__ Wk, const float* __restrict__ bk,
                           const float* __restrict__ bv) {
    __shared__ float xs[C_][28];
    __shared__ float xm[C_];
    int b = blockIdx.x; int n = b >> 9; int t = b & 511;
    int tid = threadIdx.x;
    {
        const float* xbase = x + ((size_t)n * C_ * T_ + t) * V_;
        for (int i = tid; i < C_ * V_; i += 128) {
            int c = (int)(((unsigned)i * 5243u) >> 17);
            int v = i - c * 25;
            xs[c][v] = xbase[(size_t)c * T_ * V_ + v];
        }
        xs[tid][25] = 0.f; xs[tid][26] = 0.f; xs[tid][27] = 0.f;
    }
    __syncthreads();
    int o = tid;
    {
        float s = 0.f;
#pragma unroll
        for (int v = 0; v < V_; v++) s += xs[o][v];
        xm[o] = s * (1.0f / 25.0f);
    }
    __syncthreads();

    if (o < 32) {
        int h = o & 15;
        bool isQ = o < 16;
        const float* W = isQ ? Wq : Wk;
        float acc = isQ ? bq[h] : bk[h];
#pragma unroll 8
        for (int cc = 0; cc < C_; cc++) acc += W[h * C_ + cc] * xm[cc];
        float* dst = isQ ? g_q : g_k;
        dst[(n * T_ + t) * H_ + h] = acc;
    }

    ull acc[13];
    ull binit = dup2(bv[o]);
#pragma unroll
    for (int j = 0; j < 13; j++) acc[j] = binit;
    for (int c = 0; c < C_; c++) {
        ull wd = dup2(g_wvt[c * O_ + o]);
        const ulonglong2* xr = (const ulonglong2*)xs[c];
#pragma unroll
        for (int j = 0; j < 6; j++) {
            ulonglong2 p = xr[j];
            acc[2 * j]     = ffma2(wd, p.x, acc[2 * j]);
            acc[2 * j + 1] = ffma2(wd, p.y, acc[2 * j + 1]);
        }
        acc[12] = ffma2(wd, *((const ull*)xs[c] + 12), acc[12]);
    }
    float* row = g_v + (((size_t)(n * T_ + t)) * O_ + o) * 32;
#pragma unroll
    for (int j = 0; j < 12; j++) {
        float2 u = unpack2(acc[j]);
        row[2 * j] = u.x; row[2 * j + 1] = u.y;
    }
    { float2 u = unpack2(acc[12]); row[24] = u.x; }
#pragma unroll
    for (int p = 25; p < 32; p++) row[p] = 0.f;
}

// ---------------- K2: sv_kernel — S precompute (0-511) + direct vsum (512-1023) --
__global__ void __launch_bounds__(512)
sv_kernel() {
    __shared__ float red[16][33];
    int b = blockIdx.x;
    int tid = threadIdx.x;
    if (b < 512) {
        int n = b >> 7, gt = (b >> 2) & 31, cq = b & 3;
        int g = tid >> 5, tt = (tid >> 2) & 7, hq = tid & 3;
        float4 q4 = *(const float4*)(g_q + (n * T_ + gt * 16 + g) * H_ + hq * 4);
        float* sbase = g_s + ((size_t)(n * 32 + gt)) * 64 * 2048 + tid * 4;
#pragma unroll 4
        for (int cc = cq * 16; cc < cq * 16 + 16; cc++) {
            float4 k4 = *(const float4*)(g_k + (n * T_ + cc * 8 + tt) * H_ + hq * 4);
            float4 s;
            s.x = tanh_fast(q4.x - k4.x);
            s.y = tanh_fast(q4.y - k4.y);
            s.z = tanh_fast(q4.z - k4.z);
            s.w = tanh_fast(q4.w - k4.w);
            *(float4*)(sbase + (size_t)cc * 2048) = s;
        }
    } else {
        int b2 = b - 512;
        int n = b2 >> 7, o = b2 & 127;
        int tsub = tid >> 5, comp = tid & 31;
        const float* base = g_v + (((size_t)(n * T_ + tsub * 32)) * O_ + o) * 32 + comp;
        float a0 = 0.f, a1 = 0.f, a2 = 0.f, a3 = 0.f;
#pragma unroll
        for (int u = 0; u < 32; u += 4) {
            a0 += base[(size_t)(u + 0) * O_ * 32];
            a1 += base[(size_t)(u + 1) * O_ * 32];
            a2 += base[(size_t)(u + 2) * O_ * 32];
            a3 += base[(size_t)(u + 3) * O_ * 32];
        }
        red[tsub][comp] = (a0 + a1) + (a2 + a3);
        __syncthreads();
        if (tid < 32) {
            float s = 0.f;
#pragma unroll
            for (int r = 0; r < 16; r++) s += red[r][tid];
            g_vsum[(n * O_ + o) * 32 + tid] = s;
        }
    }
}

// ---------------- K3: fused attention — warp-specialized, conflict-free B reads --
#define TCH 8
#define NCHUNK (T_ / TCH)            // 64
#define SCH 2048
#define AROWP 132
#define ABUF (16 * AROWP)            // 2112
#define SM_AS (3 * SCH)              // 6144
#define SM_TOT (SM_AS + 2 * ABUF)    // 10368 floats = 41472 B

// B stage: 2 o (oP, oP+8) x 4 g per thread.
// sw (0/1) XOR-permutes the quad read order so lanes ttB 0..3 hit disjoint banks;
// w0/w1 are pre-permuted at init to match.
__device__ __forceinline__ void b_stage2o(const float* __restrict__ Sb, float* __restrict__ Ab,
                                          const ull* __restrict__ w0, const ull* __restrict__ w1,
                                          int oP, int ttB, int gq, int sw) {
    float out0[4], out1[4];
    const float* srow = Sb + ttB * 16;
#pragma unroll
    for (int i = 0; i < 4; i++) {
        int g = gq * 4 + i;
        const ulonglong2* sp = (const ulonglong2*)(srow + g * 128);
        ulonglong2 s0 = sp[0 ^ sw], s1 = sp[1 ^ sw];
        ulonglong2 s2 = sp[2 ^ sw], s3 = sp[3 ^ sw];
        ull a0 = fmul2(w0[0], s0.x);  a0 = ffma2(w0[1], s0.y, a0);
        a0 = ffma2(w0[2], s1.x, a0);  a0 = ffma2(w0[3], s1.y, a0);
        ull a1 = fmul2(w0[4], s2.x);  a1 = ffma2(w0[5], s2.y, a1);
        a1 = ffma2(w0[6], s3.x, a1);  a1 = ffma2(w0[7], s3.y, a1);
        float2 u = unpack2(fadd2(a0, a1));
        out0[i] = u.x + u.y;
        ull b0 = fmul2(w1[0], s0.x);  b0 = ffma2(w1[1], s0.y, b0);
        b0 = ffma2(w1[2], s1.x, b0);  b0 = ffma2(w1[3], s1.y, b0);
        ull b1 = fmul2(w1[4], s2.x);  b1 = ffma2(w1[5], s2.y, b1);
        b1 = ffma2(w1[6], s3.x, b1);  b1 = ffma2(w1[7], s3.y, b1);
        float2 v = unpack2(fadd2(b0, b1));
        out1[i] = v.x + v.y;
    }
    *(float4*)(Ab + oP * AROWP + ttB * 16 + gq * 4) =
        make_float4(out0[0], out0[1], out0[2], out0[3]);
    *(float4*)(Ab + (oP + 8) * AROWP + ttB * 16 + gq * 4) =
        make_float4(out1[0], out1[1], out1[2], out1[3]);
}

__global__ void __launch_bounds__(512, 2)
attn_kernel(const float* __restrict__ Wr, const float* __restrict__ br) {
    extern __shared__ float sm[];
    float* S_s = sm;                 // 3 x 2048
    float* A_s = sm + SM_AS;         // 2 x 2112

    int bx = blockIdx.x;
    int gt = bx & 31, ot = (bx >> 5) & 7, n = bx >> 8;
    int o_base = ot * 16, g_base = gt * 16;
    int tid = threadIdx.x;

    float sum = 0.f, sq = 0.f;
    ull acc0[8], acc1[8];

    if (tid < 256) {
        // ================= B role =================
        int oP = tid & 7, ttB = (tid >> 3) & 7, gq = tid >> 6;
        int sw = (ttB >> 1) & 1;
        ull w0[8], w1[8];
        {
            const ull* wp0 = (const ull*)(Wr + (o_base + oP) * H_);
            const ull* wp1 = (const ull*)(Wr + (o_base + oP + 8) * H_);
#pragma unroll
            for (int j = 0; j < 8; j++) { w0[j] = wp0[j]; w1[j] = wp1[j]; }
            if (sw) {
                // swap pair-of-pairs: (w0w1)<->(w2w3), (w4w5)<->(w6w7)
                ull t;
                t = w0[0]; w0[0] = w0[2]; w0[2] = t;
                t = w0[1]; w0[1] = w0[3]; w0[3] = t;
                t = w0[4]; w0[4] = w0[6]; w0[6] = t;
                t = w0[5]; w0[5] = w0[7]; w0[7] = t;
                t = w1[0]; w1[0] = w1[2]; w1[2] = t;
                t = w1[1]; w1[1] = w1[3]; w1[3] = t;
                t = w1[4]; w1[4] = w1[6]; w1[6] = t;
                t = w1[5]; w1[5] = w1[7]; w1[7] = t;
            }
        }
        const float* sgb = g_s + ((size_t)(n * 32 + gt)) * 64 * SCH + tid * 8;
        float* sdb = S_s + tid * 8;

        cp16(sdb + 0 * SCH, sgb + (size_t)0 * SCH);
        cp16(sdb + 0 * SCH + 4, sgb + (size_t)0 * SCH + 4);
        CP_COMMIT();
        cp16(sdb + 1 * SCH, sgb + (size_t)1 * SCH);
        cp16(sdb + 1 * SCH + 4, sgb + (size_t)1 * SCH + 4);
        CP_COMMIT();
        cp16(sdb + 2 * SCH, sgb + (size_t)2 * SCH);
        cp16(sdb + 2 * SCH + 4, sgb + (size_t)2 * SCH + 4);
        CP_COMMIT();
        CP_WAIT2();
        __syncthreads();                         // bar 1: S0 ready
        b_stage2o(S_s, A_s, w0, w1, oP, ttB, gq, sw);   // A(0)
        CP_WAIT1();
        __syncthreads();                         // bar 2: S1 ready + A0 visible

        int sb = 0;
        for (int c = 0; c < NCHUNK; c++) {
            if (c + 3 < NCHUNK) {
                cp16(sdb + sb * SCH, sgb + (size_t)(c + 3) * SCH);
                cp16(sdb + sb * SCH + 4, sgb + (size_t)(c + 3) * SCH + 4);
            }
            CP_COMMIT();
            int rb = sb + 1; if (rb == 3) rb = 0;
            if (c + 1 < NCHUNK)
                b_stage2o(S_s + rb * SCH, A_s + ((c + 1) & 1) * ABUF, w0, w1, oP, ttB, gq, sw);
            CP_WAIT1();
            __syncthreads();                     // bars 3..66
            sb = rb;
        }
    } else {
        // ================= C role =================
        int ct = tid - 256;
        int oC = ct / 13, jC = ct - oC * 13;
        bool actC = ct < 208;
        if (!actC) { oC = 0; jC = 0; }
        const float* vbase = g_v + (((size_t)n * T_) * O_ + o_base + oC) * 32 + 2 * jC;
        ull vcur[4];
        if (actC) {
            float brv = br[o_base + oC];
            const float* vs = g_vsum + (n * O_ + o_base + oC) * 32 + 2 * jC;
            ull i0 = dup2(brv * vs[0]);
            ull i1 = dup2(brv * vs[1]);
#pragma unroll
            for (int p = 0; p < 8; p++) { acc0[p] = i0; acc1[p] = i1; }
#pragma unroll
            for (int tt = 0; tt < 4; tt++)
                vcur[tt] = *(const ull*)(vbase + (size_t)tt * O_ * 32);
        }
        __syncthreads();                         // bar 1
        __syncthreads();                         // bar 2

        for (int c = 0; c < NCHUNK; c++) {
            if (actC) {
                const float* arow = A_s + (c & 1) * ABUF + oC * AROWP;
#pragma unroll
                for (int half = 0; half < 2; half++) {
#pragma unroll
                    for (int tt = 0; tt < 4; tt++) {
                        const ulonglong2* ap =
                            (const ulonglong2*)(arow + (half * 4 + tt) * 16);
                        ulonglong2 p0 = ap[0], p1 = ap[1];
                        ulonglong2 p2 = ap[2], p3 = ap[3];
                        float2 vv = unpack2(vcur[tt]);
                        ull d0 = dup2(vv.x), d1 = dup2(vv.y);
                        acc0[0] = ffma2(p0.x, d0, acc0[0]);
                        acc0[1] = ffma2(p0.y, d0, acc0[1]);
                        acc0[2] = ffma2(p1.x, d0, acc0[2]);
                        acc0[3] = ffma2(p1.y, d0, acc0[3]);
                        acc0[4] = ffma2(p2.x, d0, acc0[4]);
                        acc0[5] = ffma2(p2.y, d0, acc0[5]);
                        acc0[6] = ffma2(p3.x, d0, acc0[6]);
                        acc0[7] = ffma2(p3.y, d0, acc0[7]);
                        acc1[0] = ffma2(p0.x, d1, acc1[0]);
                        acc1[1] = ffma2(p0.y, d1, acc1[1]);
                        acc1[2] = ffma2(p1.x, d1, acc1[2]);
                        acc1[3] = ffma2(p1.y, d1, acc1[3]);
                        acc1[4] = ffma2(p2.x, d1, acc1[4]);
                        acc1[5] = ffma2(p2.y, d1, acc1[5]);
                        acc1[6] = ffma2(p3.x, d1, acc1[6]);
                        acc1[7] = ffma2(p3.y, d1, acc1[7]);
                    }
                    const float* vnx = (half == 0)
                        ? vbase + ((size_t)c * TCH + 4) * O_ * 32
                        : vbase + ((size_t)(c + 1) * TCH) * O_ * 32;
                    if (half == 0 || c + 1 < NCHUNK) {
#pragma unroll
                        for (int tt = 0; tt < 4; tt++)
                            vcur[tt] = *(const ull*)(vnx + (size_t)tt * O_ * 32);
                    }
                }
            }
            __syncthreads();                     // bars 3..66
        }

        if (actC) {
            int o0 = o_base + oC;
            float* ybase = g_y + (((size_t)(n * O_ + o0)) * T_ + g_base) * 26 + 2 * jC;
#pragma unroll
            for (int p = 0; p < 8; p++) {
                float2 u0 = unpack2(acc0[p]);
                float2 u1 = unpack2(acc1[p]);
                *(ull*)(ybase + (2 * p) * 26)     = pack2(u0.x, u1.x);
                *(ull*)(ybase + (2 * p + 1) * 26) = pack2(u0.y, u1.y);
                sum += u0.x + u0.y + u1.x + u1.y;
                sq  += u0.x * u0.x + u0.y * u0.y + u1.x * u1.x + u1.y * u1.y;
            }
        }
    }

    // ---- common epilogue: BN stat reduction ----
    float* red = sm;
    if (tid < 32) red[tid] = 0.f;
    __syncthreads();
    if (tid >= 256 && (tid - 256) < 208) {
        int oC = (tid - 256) / 13;
        atomicAdd(&red[oC], sum);
        atomicAdd(&red[16 + oC], sq);
    }
    __syncthreads();
    if (tid < 16)       atomicAdd(&g_chsum[o_base + tid], red[tid]);
    else if (tid < 32)  atomicAdd(&g_chsq[o_base + tid - 16], red[tid]);
}

// ---------------- K4: BN + residual + ReLU ----------------------------------------
__global__ void bn_kernel(const float* __restrict__ x,
                          const float* __restrict__ gamma, const float* __restrict__ beta,
                          float* __restrict__ out) {
    int bx = blockIdx.x;
    int n = bx >> 7, o = bx & 127;
    int tid = threadIdx.x;
    float mu  = g_chsum[o] * (1.0f / YCNT);
    float var = g_chsq[o] * (1.0f / YCNT) - mu * mu;
    float r = rsqrtf(var + EPS_);
    float gam = gamma[o] * r;
    float bet = beta[o] - mu * gam;
    const float* xb = x + (((size_t)(n * C_ + o)) * T_) * V_;
    const float* yb = g_y + ((size_t)(n * O_ + o)) * T_ * 26;
    float* ob = out + (((size_t)(n * O_ + o)) * T_) * V_;
#pragma unroll
    for (int i = 0; i < 25; i++) {
        int e = tid + i * 512;
        int t = (int)(((unsigned)e * 5243u) >> 17);
        float yv = yb[e + t];
        float val = yv * gam + bet + xb[e];
        ob[e] = fmaxf(val, 0.f);
    }
}

// ---------------- launcher ----------------------------------------------------------
extern "C" void kernel_launch(void* const* d_in, const int* in_sizes, int n_in,
                              void* d_out, int out_size) {
    const float* x     = (const float*)d_in[0];
    const float* Wq    = (const float*)d_in[1];
    const float* bq    = (const float*)d_in[2];
    const float* Wk    = (const float*)d_in[3];
    const float* bk    = (const float*)d_in[4];
    const float* Wv    = (const float*)d_in[5];
    const float* bv    = (const float*)d_in[6];
    const float* Wr    = (const float*)d_in[7];
    const float* br    = (const float*)d_in[8];
    const float* gamma = (const float*)d_in[9];
    const float* beta  = (const float*)d_in[10];
    float* out = (float*)d_out;

    const int smem_bytes = SM_TOT * 4;   // 41472
    cudaFuncSetAttribute(attn_kernel, cudaFuncAttributeMaxDynamicSharedMemorySize, smem_bytes);

    prep_kernel<<<128, 128>>>(Wv);                              // 1
    qkv_kernel<<<N_ * T_, 128>>>(x, Wq, bq, Wk, bk, bv);        // 2
    sv_kernel<<<1024, 512>>>();                                 // 3
    attn_kernel<<<1024, 512, smem_bytes>>>(Wr, br);             // 4  <- profiled
    bn_kernel<<<512, 512>>>(x, gamma, beta, out);               // 5
}